// round 3
// baseline (speedup 1.0000x reference)
#include <cuda_runtime.h>
#include <cstdint>

// ============================================================================
// CourierEncoder fused MLP for sm_103 (no 'a' features available from the
// harness's compute_103 virtual arch) -> Ampere-style mma.sync tf32 path.
//   emb[B,384] -> h1 = lrelu(emb@w1+b1) -> out = lrelu(h1@w2+b2)
// CTA = 128 rows. 8 warps in 2(M64) x 4(N64) grid. 128 f32 acc per lane.
// A (emb / h1) lives in one 128x(stride 388) f32 smem buffer.
// B (weights) pre-transposed + tf32-rounded + frag-pair permuted in gmem.
// ============================================================================

static constexpr int   ASTRIDE    = 388;      // f32 words per row (pad vs 384)
static constexpr float NEG_SLOPEF = 0.01f;

// weight scratch, prepared once per launch by courier_prep
__device__ float g_w1T[256 * 384];   // [n][permuted k], K=384
__device__ float g_w2T[256 * 256];   // [n][permuted k], K=256

// ---- smem layout (f32 words after the A buffer) ----
static constexpr int SM_A_WORDS = 128 * ASTRIDE;           // 49664 words
static constexpr int SM_FR   = SM_A_WORDS;                 // 512: wsx,bsx,wcx,bcx,wsy,bsy,wcy,bcy (8x64)
static constexpr int SM_WT   = SM_FR + 512;                // 128
static constexpr int SM_BT   = SM_WT + 128;                // 128
static constexpr int SM_B1   = SM_BT + 128;                // 256
static constexpr int SM_B2   = SM_B1 + 256;                // 256
static constexpr int SM_X    = SM_B2 + 256;                // 128
static constexpr int SM_Y    = SM_X + 128;                 // 128
static constexpr int SM_T    = SM_Y + 128;                 // 128
static constexpr int SMEM_WORDS = SM_T + 128;
static constexpr int SMEM_BYTES = SMEM_WORDS * 4;          // ~205 KB

__device__ __forceinline__ uint32_t f2tf32(float f) {
    uint32_t u;
    asm("cvt.rna.tf32.f32 %0, %1;" : "=r"(u) : "f"(f));
    return u;
}
__device__ __forceinline__ float lrelu(float v) {
    return v >= 0.f ? v : NEG_SLOPEF * v;
}
__device__ __forceinline__ void mma8(float* c, const uint32_t* a, const uint32_t* b) {
    asm volatile(
        "mma.sync.aligned.m16n8k8.row.col.f32.tf32.tf32.f32 "
        "{%0,%1,%2,%3}, {%4,%5,%6,%7}, {%8,%9}, {%0,%1,%2,%3};"
        : "+f"(c[0]), "+f"(c[1]), "+f"(c[2]), "+f"(c[3])
        : "r"(a[0]), "r"(a[1]), "r"(a[2]), "r"(a[3]), "r"(b[0]), "r"(b[1]));
}

// ---------------------------------------------------------------- prep kernel
// Transpose weights to [n][k], tf32-round, and permute k so that one mma B
// fragment (b0: k, b1: k+4 for k in kstep*8 + 0..3) is 8 contiguous bytes:
//   dst[n*K + s*8 + km4*2 + h] = w[(s*8 + km4 + 4h)*256 + n]
__global__ void courier_prep(const float* __restrict__ w1, const float* __restrict__ w2) {
    int i = blockIdx.x * blockDim.x + threadIdx.x;
    if (i < 256 * 384) {
        int n = i / 384, rem = i % 384;
        int s = rem >> 3, q = rem & 7;
        int k = s * 8 + (q >> 1) + 4 * (q & 1);
        g_w1T[i] = __uint_as_float(f2tf32(w1[k * 256 + n]));
    }
    int j = i - 256 * 384;
    if (j >= 0 && j < 256 * 256) {
        int n = j / 256, rem = j % 256;
        int s = rem >> 3, q = rem & 7;
        int k = s * 8 + (q >> 1) + 4 * (q & 1);
        g_w2T[j] = __uint_as_float(f2tf32(w2[k * 256 + n]));
    }
}

// ---------------------------------------------------------------- gemm core
// One layer: D[128,256] += A[128,K](smem, stride ASTRIDE) * W[K,256](gmem,
// permuted [n][k]). Each warp owns a 64x64 tile: warp_m in {0,1}, warp_n 0..3.
template <int K>
__device__ __forceinline__ void gemm_layer(const float* __restrict__ Wg,
                                           const float* __restrict__ smA,
                                           int warp_m, int warp_n, int lane,
                                           float acc[4][8][4]) {
    constexpr int KS = K / 8;
    const int g = lane >> 2;      // group id 0..7
    const int tg = lane & 3;      // thread-in-group 0..3

    // B: frag nf, kstep s -> 8 bytes at (warp_n*64 + nf*8 + g)*K + s*8 + tg*2
    const float* bbase = Wg + (size_t)(warp_n * 64 + g) * K + tg * 2;
    // A: frag mf, kstep s -> scalars at (warp_m*64 + mf*16 + g (+8))*ASTRIDE
    //                                  + s*8 + tg (+4)
    const float* abase = smA + (warp_m * 64 + g) * ASTRIDE + tg;

    uint32_t bb[2][8][2];
#pragma unroll
    for (int nf = 0; nf < 8; nf++) {
        float2 v = *(const float2*)(bbase + nf * 8 * K);
        bb[0][nf][0] = __float_as_uint(v.x);
        bb[0][nf][1] = __float_as_uint(v.y);
    }

#pragma unroll 2
    for (int s = 0; s < KS; s++) {
        const int cur = s & 1;
        if (s + 1 < KS) {
#pragma unroll
            for (int nf = 0; nf < 8; nf++) {
                float2 v = *(const float2*)(bbase + nf * 8 * K + (s + 1) * 8);
                bb[cur ^ 1][nf][0] = __float_as_uint(v.x);
                bb[cur ^ 1][nf][1] = __float_as_uint(v.y);
            }
        }
        uint32_t a[4][4];
#pragma unroll
        for (int mf = 0; mf < 4; mf++) {
            const float* ap = abase + mf * 16 * ASTRIDE + s * 8;
            a[mf][0] = __float_as_uint(ap[0]);
            a[mf][1] = __float_as_uint(ap[8 * ASTRIDE]);
            a[mf][2] = __float_as_uint(ap[4]);
            a[mf][3] = __float_as_uint(ap[8 * ASTRIDE + 4]);
        }
#pragma unroll
        for (int mf = 0; mf < 4; mf++)
#pragma unroll
            for (int nf = 0; nf < 8; nf++)
                mma8(acc[mf][nf], a[mf], bb[cur][nf]);
    }
}

// ---------------------------------------------------------------- main kernel
__global__ __launch_bounds__(256, 1)
void courier_main(const float* __restrict__ xy, const float* __restrict__ tin,
                  const float* __restrict__ w_sx, const float* __restrict__ b_sx,
                  const float* __restrict__ w_cx, const float* __restrict__ b_cx,
                  const float* __restrict__ w_sy, const float* __restrict__ b_sy,
                  const float* __restrict__ w_cy, const float* __restrict__ b_cy,
                  const float* __restrict__ w_t,  const float* __restrict__ b_t,
                  const float* __restrict__ b1,   const float* __restrict__ b2,
                  float* __restrict__ out) {
    extern __shared__ float sm[];
    float* smA   = sm;
    float* sm_fr = sm + SM_FR;
    float* sm_wt = sm + SM_WT;
    float* sm_bt = sm + SM_BT;
    float* sm_b1 = sm + SM_B1;
    float* sm_b2 = sm + SM_B2;
    float* sm_x  = sm + SM_X;
    float* sm_y  = sm + SM_Y;
    float* sm_t  = sm + SM_T;

    const int tid    = threadIdx.x;
    const int lane   = tid & 31;
    const int wid    = tid >> 5;
    const int warp_m = wid >> 2;   // 0,1
    const int warp_n = wid & 3;    // 0..3

    // ---- stage small params + per-row inputs ----
    if (tid < 128) {
        int row = blockIdx.x * 128 + tid;
        float2 p = *(const float2*)(xy + 2 * row);
        sm_x[tid]  = p.x;
        sm_y[tid]  = p.y;
        sm_t[tid]  = tin[row];
        sm_wt[tid] = w_t[tid];
        sm_bt[tid] = b_t[tid];
    }
    if (tid < 64) {
        sm_fr[tid]       = w_sx[tid];  sm_fr[64 + tid]  = b_sx[tid];
        sm_fr[128 + tid] = w_cx[tid];  sm_fr[192 + tid] = b_cx[tid];
        sm_fr[256 + tid] = w_sy[tid];  sm_fr[320 + tid] = b_sy[tid];
        sm_fr[384 + tid] = w_cy[tid];  sm_fr[448 + tid] = b_cy[tid];
    }
    sm_b1[tid] = b1[tid];
    sm_b2[tid] = b2[tid];
    __syncthreads();

    // ---- generate embedding A1 [128 x 384] (tf32-rounded) ----
    {
        const int r    = tid >> 1;       // 2 threads per row
        const int half = tid & 1;        // cols [half*192, half*192+192)
        const float xv = sm_x[r];
        const float yv = sm_y[r];
        const float tv = sm_t[r];
        float* arow = smA + r * ASTRIDE + half * 192;
#pragma unroll 4
        for (int j = 0; j < 192; j++) {
            int c = half * 192 + j;
            float v;
            if (c < 64)       v = __sinf(fmaf(xv, sm_fr[c],       sm_fr[64 + c]));
            else if (c < 128) v = __cosf(fmaf(xv, sm_fr[64 + c],  sm_fr[128 + c]));
            else if (c < 192) v = __sinf(fmaf(yv, sm_fr[128 + c], sm_fr[192 + c]));
            else if (c < 256) v = __cosf(fmaf(yv, sm_fr[192 + c], sm_fr[256 + c]));
            else              v = lrelu(fmaf(tv, sm_wt[c - 256],  sm_bt[c - 256]));
            arow[j] = __uint_as_float(f2tf32(v));
        }
    }
    __syncthreads();

    // ---- layer 1: h1 = lrelu(A1 @ w1 + b1), K=384 ----
    float acc[4][8][4];
#pragma unroll
    for (int mf = 0; mf < 4; mf++)
#pragma unroll
        for (int nf = 0; nf < 8; nf++)
#pragma unroll
            for (int j = 0; j < 4; j++) acc[mf][nf][j] = 0.f;

    gemm_layer<384>(g_w1T, smA, warp_m, warp_n, lane, acc);
    __syncthreads();   // everyone done reading A1

    // ---- epilogue 1: bias + lrelu + tf32, write h1 into smA ----
    {
        const int g  = lane >> 2;
        const int tg = lane & 3;
#pragma unroll
        for (int mf = 0; mf < 4; mf++) {
#pragma unroll
            for (int nf = 0; nf < 8; nf++) {
                int row = warp_m * 64 + mf * 16 + g;
                int col = warp_n * 64 + nf * 8 + 2 * tg;
                float2 v0, v1;
                v0.x = __uint_as_float(f2tf32(lrelu(acc[mf][nf][0] + sm_b1[col])));
                v0.y = __uint_as_float(f2tf32(lrelu(acc[mf][nf][1] + sm_b1[col + 1])));
                v1.x = __uint_as_float(f2tf32(lrelu(acc[mf][nf][2] + sm_b1[col])));
                v1.y = __uint_as_float(f2tf32(lrelu(acc[mf][nf][3] + sm_b1[col + 1])));
                *(float2*)(smA + row * ASTRIDE + col)       = v0;
                *(float2*)(smA + (row + 8) * ASTRIDE + col) = v1;
            }
        }
    }
    __syncthreads();

    // ---- layer 2: out = lrelu(h1 @ w2 + b2), K=256 ----
#pragma unroll
    for (int mf = 0; mf < 4; mf++)
#pragma unroll
        for (int nf = 0; nf < 8; nf++)
#pragma unroll
            for (int j = 0; j < 4; j++) acc[mf][nf][j] = 0.f;

    gemm_layer<256>(g_w2T, smA, warp_m, warp_n, lane, acc);

    // ---- final epilogue: bias + lrelu, STG.64 direct to gmem ----
    {
        const int g  = lane >> 2;
        const int tg = lane & 3;
        float* obase = out + (size_t)blockIdx.x * 128 * 256;
#pragma unroll
        for (int mf = 0; mf < 4; mf++) {
#pragma unroll
            for (int nf = 0; nf < 8; nf++) {
                int row = warp_m * 64 + mf * 16 + g;
                int col = warp_n * 64 + nf * 8 + 2 * tg;
                float2 v0, v1;
                v0.x = lrelu(acc[mf][nf][0] + sm_b2[col]);
                v0.y = lrelu(acc[mf][nf][1] + sm_b2[col + 1]);
                v1.x = lrelu(acc[mf][nf][2] + sm_b2[col]);
                v1.y = lrelu(acc[mf][nf][3] + sm_b2[col + 1]);
                *(float2*)(obase + row * 256 + col)       = v0;
                *(float2*)(obase + (row + 8) * 256 + col) = v1;
            }
        }
    }
}

// ---------------------------------------------------------------- launcher
extern "C" void kernel_launch(void* const* d_in, const int* in_sizes, int n_in,
                              void* d_out, int out_size) {
    const float* xy   = (const float*)d_in[0];
    const float* t    = (const float*)d_in[1];
    const float* w_sx = (const float*)d_in[2];
    const float* b_sx = (const float*)d_in[3];
    const float* w_cx = (const float*)d_in[4];
    const float* b_cx = (const float*)d_in[5];
    const float* w_sy = (const float*)d_in[6];
    const float* b_sy = (const float*)d_in[7];
    const float* w_cy = (const float*)d_in[8];
    const float* b_cy = (const float*)d_in[9];
    const float* w_t  = (const float*)d_in[10];
    const float* b_t  = (const float*)d_in[11];
    const float* w1   = (const float*)d_in[12];
    const float* b1   = (const float*)d_in[13];
    const float* w2   = (const float*)d_in[14];
    const float* b2   = (const float*)d_in[15];
    float* out = (float*)d_out;

    courier_prep<<<640, 256>>>(w1, w2);

    static bool attr_set = false;
    if (!attr_set) {
        cudaFuncSetAttribute(courier_main, cudaFuncAttributeMaxDynamicSharedMemorySize,
                             SMEM_BYTES);
        attr_set = true;
    }

    courier_main<<<2048, 256, SMEM_BYTES>>>(xy, t, w_sx, b_sx, w_cx, b_cx,
                                            w_sy, b_sy, w_cy, b_cy,
                                            w_t, b_t, b1, b2, out);
}

// round 4
// speedup vs baseline: 1.0925x; 1.0925x over previous
#include <cuda_runtime.h>
#include <cstdint>

// ============================================================================
// CourierEncoder fused MLP, sm_103 (plain target) mma.sync tf32 path, round 4.
//   emb[B,384] -> h1 = lrelu(emb@w1+b1) -> out = lrelu(h1@w2+b2)
// CTA = 128 rows, 512 threads = 16 warps in 2(M64) x 8(N32) grid.
// Warp tile 64x32: mf=4, nf=4, 64 f32 accs/lane.
// A lives in smem in FRAGMENT-MAJOR packed layout: for (mtile, kstep) the
// 128 f32 fragment words are stored as 32 lanes x float4 -> one LDS.128 per
// (mf, s) per warp, conflict-free.
// k-space is relabeled by pi(8s+4*hh+tq) = 8s+2*tq+hh, which makes the
// layer-1 epilogue write thread-local STS.128 AND reduces both weight preps
// to plain transposes (pi cancels against the mma B-fragment layout).
// ============================================================================

static constexpr float NEG_SLOPEF = 0.01f;
static constexpr int KS1 = 48;   // 384/8 k-steps, layer 1
static constexpr int KS2 = 32;   // 256/8 k-steps, layer 2

// weight scratch: [n][k] transposed + tf32-rounded
__device__ float g_w1T[256 * 384];
__device__ float g_w2T[256 * 256];

// ---- smem layout (f32 words) ----
static constexpr int SM_A    = 0;                    // packed A: 8*48*32*4 = 49152 words
static constexpr int SM_FR   = 49152;                // 512: wsx,bsx,wcx,bcx,wsy,bsy,wcy,bcy
static constexpr int SM_WT   = SM_FR + 512;          // 128
static constexpr int SM_BT   = SM_WT + 128;          // 128
static constexpr int SM_B1   = SM_BT + 128;          // 256
static constexpr int SM_B2   = SM_B1 + 256;          // 256
static constexpr int SM_X    = SM_B2 + 256;          // 128
static constexpr int SM_Y    = SM_X + 128;           // 128
static constexpr int SM_T    = SM_Y + 128;           // 128
static constexpr int SMEM_WORDS = SM_T + 128;
static constexpr int SMEM_BYTES = SMEM_WORDS * 4;    // 203264 B

__device__ __forceinline__ uint32_t f2tf32(float f) {
    uint32_t u;
    asm("cvt.rna.tf32.f32 %0, %1;" : "=r"(u) : "f"(f));
    return u;
}
__device__ __forceinline__ float lrelu(float v) { return v >= 0.f ? v : NEG_SLOPEF * v; }

__device__ __forceinline__ void mma8(float* c, const uint32_t* a, const uint32_t* b) {
    asm volatile(
        "mma.sync.aligned.m16n8k8.row.col.f32.tf32.tf32.f32 "
        "{%0,%1,%2,%3}, {%4,%5,%6,%7}, {%8,%9}, {%0,%1,%2,%3};"
        : "+f"(c[0]), "+f"(c[1]), "+f"(c[2]), "+f"(c[3])
        : "r"(a[0]), "r"(a[1]), "r"(a[2]), "r"(a[3]), "r"(b[0]), "r"(b[1]));
}

// ---------------------------------------------------------------- prep kernel
// Plain transpose + tf32 round (the fragment permutation cancels under pi).
__global__ void courier_prep(const float* __restrict__ w1, const float* __restrict__ w2) {
    int i = blockIdx.x * blockDim.x + threadIdx.x;
    if (i < 256 * 384) {
        int n = i / 384, k = i % 384;
        g_w1T[i] = __uint_as_float(f2tf32(w1[k * 256 + n]));
    }
    int j = i - 256 * 384;
    if (j >= 0 && j < 256 * 256) {
        int n = j / 256, k = j % 256;
        g_w2T[j] = __uint_as_float(f2tf32(w2[k * 256 + n]));
    }
}

// ---------------------------------------------------------------- gemm core
// D[128,256] += A_packed * W[n][k].  Warp tile 64x32 at (warp_m, warp_n).
// B fragment (nf, s): float2 at (warp_n*32 + nf*8 + g)*K + s*8 + tg*2,
// giving b0 = pi-k (8s+tg), b1 = pi-k (8s+4+tg)  [orig k 8s+2tg, 8s+2tg+1].
template <int KS>
__device__ __forceinline__ void gemm_layer(const float* __restrict__ Wg,
                                           const float4* __restrict__ smA4,
                                           int warp_m, int warp_n, int lane,
                                           float acc[4][4][4]) {
    constexpr int K = KS * 8;
    const int g  = lane >> 2;
    const int tg = lane & 3;
    const float* bbase = Wg + (size_t)(warp_n * 32 + g) * K + tg * 2;

    uint32_t bb[2][4][2];
#pragma unroll
    for (int nf = 0; nf < 4; nf++) {
        float2 v0 = *(const float2*)(bbase + nf * 8 * K);
        float2 v1 = *(const float2*)(bbase + nf * 8 * K + 8);
        bb[0][nf][0] = __float_as_uint(v0.x); bb[0][nf][1] = __float_as_uint(v0.y);
        bb[1][nf][0] = __float_as_uint(v1.x); bb[1][nf][1] = __float_as_uint(v1.y);
    }

#pragma unroll 2
    for (int s = 0; s < KS; s++) {
        const int cur = s & 1;
        uint32_t a[4][4];
#pragma unroll
        for (int mf = 0; mf < 4; mf++) {
            float4 av = smA4[((warp_m * 4 + mf) * KS + s) * 32 + lane];
            a[mf][0] = __float_as_uint(av.x);
            a[mf][1] = __float_as_uint(av.y);
            a[mf][2] = __float_as_uint(av.z);
            a[mf][3] = __float_as_uint(av.w);
        }
#pragma unroll
        for (int mf = 0; mf < 4; mf++)
#pragma unroll
            for (int nf = 0; nf < 4; nf++)
                mma8(acc[mf][nf], a[mf], bb[cur][nf]);
        if (s + 2 < KS) {
#pragma unroll
            for (int nf = 0; nf < 4; nf++) {
                float2 v = *(const float2*)(bbase + nf * 8 * K + (s + 2) * 8);
                bb[cur][nf][0] = __float_as_uint(v.x);
                bb[cur][nf][1] = __float_as_uint(v.y);
            }
        }
    }
}

// ---------------------------------------------------------------- main kernel
__global__ __launch_bounds__(512, 1)
void courier_main(const float* __restrict__ xy, const float* __restrict__ tin,
                  const float* __restrict__ w_sx, const float* __restrict__ b_sx,
                  const float* __restrict__ w_cx, const float* __restrict__ b_cx,
                  const float* __restrict__ w_sy, const float* __restrict__ b_sy,
                  const float* __restrict__ w_cy, const float* __restrict__ b_cy,
                  const float* __restrict__ w_t,  const float* __restrict__ b_t,
                  const float* __restrict__ b1,   const float* __restrict__ b2,
                  float* __restrict__ out) {
    extern __shared__ float sm[];
    float*  smA  = sm + SM_A;
    float4* smA4 = (float4*)smA;
    float* sm_fr = sm + SM_FR;
    float* sm_wt = sm + SM_WT;
    float* sm_bt = sm + SM_BT;
    float* sm_b1 = sm + SM_B1;
    float* sm_b2 = sm + SM_B2;
    float* sm_x  = sm + SM_X;
    float* sm_y  = sm + SM_Y;
    float* sm_t  = sm + SM_T;

    const int tid    = threadIdx.x;
    const int lane   = tid & 31;
    const int wid    = tid >> 5;          // 0..15
    const int warp_m = wid >> 3;          // 0,1
    const int warp_n = wid & 7;           // 0..7

    // ---- stage small params + per-row inputs ----
    if (tid < 128) {
        int row = blockIdx.x * 128 + tid;
        float2 p = *(const float2*)(xy + 2 * row);
        sm_x[tid]  = p.x;
        sm_y[tid]  = p.y;
        sm_t[tid]  = tin[row];
        sm_wt[tid] = w_t[tid];
        sm_bt[tid] = b_t[tid];
    }
    if (tid < 64) {
        sm_fr[tid]       = w_sx[tid];  sm_fr[64 + tid]  = b_sx[tid];
        sm_fr[128 + tid] = w_cx[tid];  sm_fr[192 + tid] = b_cx[tid];
        sm_fr[256 + tid] = w_sy[tid];  sm_fr[320 + tid] = b_sy[tid];
        sm_fr[384 + tid] = w_cy[tid];  sm_fr[448 + tid] = b_cy[tid];
    }
    if (tid < 256) {
        sm_b1[tid] = b1[tid];
        sm_b2[tid] = b2[tid];
    }
    __syncthreads();

    // ---- generate embedding A1, packed layout, tf32-rounded ----
    // 4 threads per row, 96 cols each. pi-packed store:
    //   s=c>>3, o=c&7, tq=o>>1, hh=o&1
    //   word = ((mtile*KS1 + s)*32 + g*4 + tq)*4 + h + 2*hh
    {
        const int r  = tid >> 2;
        const int q4 = tid & 3;
        const float xv = sm_x[r];
        const float yv = sm_y[r];
        const float tv = sm_t[r];
        const int mtile = r >> 4, h = (r >> 3) & 1, g = r & 7;
        const int lanebase = g * 4;
#pragma unroll 8
        for (int j = 0; j < 96; j++) {
            int c = q4 * 96 + j;
            float v;
            if (c < 64) {
                v = __sinf(fmaf(xv, sm_fr[c], sm_fr[64 + c]));
            } else if (c < 128) {
                int i = c - 64;
                v = __cosf(fmaf(xv, sm_fr[128 + i], sm_fr[192 + i]));
            } else if (c < 192) {
                int i = c - 128;
                v = __sinf(fmaf(yv, sm_fr[256 + i], sm_fr[320 + i]));
            } else if (c < 256) {
                int i = c - 192;
                v = __cosf(fmaf(yv, sm_fr[384 + i], sm_fr[448 + i]));
            } else {
                int i = c - 256;
                v = lrelu(fmaf(tv, sm_wt[i], sm_bt[i]));
            }
            int s = c >> 3, o = c & 7, tq = o >> 1, hh = o & 1;
            smA[(((mtile * KS1 + s) * 32 + lanebase + tq) << 2) + h + 2 * hh] =
                __uint_as_float(f2tf32(v));
        }
    }
    __syncthreads();

    // ---- layer 1 ----
    float acc[4][4][4];
#pragma unroll
    for (int mf = 0; mf < 4; mf++)
#pragma unroll
        for (int nf = 0; nf < 4; nf++)
#pragma unroll
            for (int j = 0; j < 4; j++) acc[mf][nf][j] = 0.f;

    gemm_layer<KS1>(g_w1T, smA4, warp_m, warp_n, lane, acc);
    __syncthreads();   // all layer-1 A reads done before overwrite

    // ---- epilogue 1: bias + lrelu + tf32 -> packed A2, thread-local STS.128 ----
    // d frags: c0=(g,2tg) c1=(g,2tg+1) c2=(g+8,2tg) c3=(g+8,2tg+1)
    // packed positions (p = h + 2*hh with hh = low col bit): {c0,c2,c1,c3}
    {
        const int tg = lane & 3;
#pragma unroll
        for (int mf = 0; mf < 4; mf++) {
#pragma unroll
            for (int nf = 0; nf < 4; nf++) {
                int col = warp_n * 32 + nf * 8 + 2 * tg;
                float4 st;
                st.x = __uint_as_float(f2tf32(lrelu(acc[mf][nf][0] + sm_b1[col])));
                st.y = __uint_as_float(f2tf32(lrelu(acc[mf][nf][2] + sm_b1[col])));
                st.z = __uint_as_float(f2tf32(lrelu(acc[mf][nf][1] + sm_b1[col + 1])));
                st.w = __uint_as_float(f2tf32(lrelu(acc[mf][nf][3] + sm_b1[col + 1])));
                int s2 = warp_n * 4 + nf;                     // kstep in layer-2 space
                smA4[((warp_m * 4 + mf) * KS2 + s2) * 32 + lane] = st;
            }
        }
    }
    __syncthreads();

    // ---- layer 2 ----
#pragma unroll
    for (int mf = 0; mf < 4; mf++)
#pragma unroll
        for (int nf = 0; nf < 4; nf++)
#pragma unroll
            for (int j = 0; j < 4; j++) acc[mf][nf][j] = 0.f;

    gemm_layer<KS2>(g_w2T, smA4, warp_m, warp_n, lane, acc);

    // ---- final epilogue: bias + lrelu, float2 stores to gmem ----
    {
        const int g  = lane >> 2;
        const int tg = lane & 3;
        float* obase = out + (size_t)blockIdx.x * 128 * 256;
#pragma unroll
        for (int mf = 0; mf < 4; mf++) {
#pragma unroll
            for (int nf = 0; nf < 4; nf++) {
                int row = warp_m * 64 + mf * 16 + g;
                int col = warp_n * 32 + nf * 8 + 2 * tg;
                float2 v0, v1;
                v0.x = lrelu(acc[mf][nf][0] + sm_b2[col]);
                v0.y = lrelu(acc[mf][nf][1] + sm_b2[col + 1]);
                v1.x = lrelu(acc[mf][nf][2] + sm_b2[col]);
                v1.y = lrelu(acc[mf][nf][3] + sm_b2[col + 1]);
                *(float2*)(obase + row * 256 + col)       = v0;
                *(float2*)(obase + (row + 8) * 256 + col) = v1;
            }
        }
    }
}

// ---------------------------------------------------------------- launcher
extern "C" void kernel_launch(void* const* d_in, const int* in_sizes, int n_in,
                              void* d_out, int out_size) {
    const float* xy   = (const float*)d_in[0];
    const float* t    = (const float*)d_in[1];
    const float* w_sx = (const float*)d_in[2];
    const float* b_sx = (const float*)d_in[3];
    const float* w_cx = (const float*)d_in[4];
    const float* b_cx = (const float*)d_in[5];
    const float* w_sy = (const float*)d_in[6];
    const float* b_sy = (const float*)d_in[7];
    const float* w_cy = (const float*)d_in[8];
    const float* b_cy = (const float*)d_in[9];
    const float* w_t  = (const float*)d_in[10];
    const float* b_t  = (const float*)d_in[11];
    const float* w1   = (const float*)d_in[12];
    const float* b1   = (const float*)d_in[13];
    const float* w2   = (const float*)d_in[14];
    const float* b2   = (const float*)d_in[15];
    float* out = (float*)d_out;

    courier_prep<<<640, 256>>>(w1, w2);

    static bool attr_set = false;
    if (!attr_set) {
        cudaFuncSetAttribute(courier_main, cudaFuncAttributeMaxDynamicSharedMemorySize,
                             SMEM_BYTES);
        attr_set = true;
    }

    courier_main<<<2048, 512, SMEM_BYTES>>>(xy, t, w_sx, b_sx, w_cx, b_cx,
                                            w_sy, b_sy, w_cy, b_cy,
                                            w_t, b_t, b1, b2, out);
}

// round 5
// speedup vs baseline: 1.3243x; 1.2122x over previous
#include <cuda_runtime.h>
#include <cstdint>

// ============================================================================
// CourierEncoder fused MLP, sm_103 plain-target mma.sync tf32 path, round 5.
//   emb[B,384] -> h1 = lrelu(emb@w1+b1) -> out = lrelu(h1@w2+b2)
// CTA = 128 rows, 512 threads = 16 warps in 2(M64) x 8(N32) grid.
// Warp tile 64x32: mf=4, nf=4, 64 f32 accs/lane.
// A: fragment-major packed smem layout -> one conflict-free LDS.128 per
//    (mf, kstep) per warp.
// B: fragment-BLOCKED gmem layout (prep kernel): for (ntile8, kstep-pair) a
//    512B block of 32 lanes x float4 -> one fully-coalesced LDG.128 feeds
//    TWO k-steps (4 L1 wavefronts instead of 16).
// ============================================================================

static constexpr float NEG_SLOPEF = 0.01f;
static constexpr int KS1 = 48;   // 384/8 k-steps, layer 1
static constexpr int KS2 = 32;   // 256/8 k-steps, layer 2
static constexpr int SP1 = KS1 / 2;
static constexpr int SP2 = KS2 / 2;

// fragment-blocked weights: [n8][sp][lane] float4, tf32-rounded
__device__ float4 g_w1B[32 * SP1 * 32];   // 32 ntiles * 24 sp * 32 lanes
__device__ float4 g_w2B[32 * SP2 * 32];   // 32 ntiles * 16 sp * 32 lanes

// ---- smem layout (f32 words) ----
static constexpr int SM_A    = 0;                    // packed A: 8*48*32*4 = 49152 words
static constexpr int SM_FR   = 49152;
static constexpr int SM_WT   = SM_FR + 512;
static constexpr int SM_BT   = SM_WT + 128;
static constexpr int SM_B1   = SM_BT + 128;
static constexpr int SM_B2   = SM_B1 + 256;
static constexpr int SM_X    = SM_B2 + 256;
static constexpr int SM_Y    = SM_X + 128;
static constexpr int SM_T    = SM_Y + 128;
static constexpr int SMEM_WORDS = SM_T + 128;
static constexpr int SMEM_BYTES = SMEM_WORDS * 4;    // ~199 KB

__device__ __forceinline__ uint32_t f2tf32(float f) {
    uint32_t u;
    asm("cvt.rna.tf32.f32 %0, %1;" : "=r"(u) : "f"(f));
    return u;
}
__device__ __forceinline__ float lrelu(float v) { return v >= 0.f ? v : NEG_SLOPEF * v; }

__device__ __forceinline__ void mma8(float* c, const uint32_t* a, uint32_t b0, uint32_t b1) {
    asm volatile(
        "mma.sync.aligned.m16n8k8.row.col.f32.tf32.tf32.f32 "
        "{%0,%1,%2,%3}, {%4,%5,%6,%7}, {%8,%9}, {%0,%1,%2,%3};"
        : "+f"(c[0]), "+f"(c[1]), "+f"(c[2]), "+f"(c[3])
        : "r"(a[0]), "r"(a[1]), "r"(a[2]), "r"(a[3]), "r"(b0), "r"(b1));
}

// ---------------------------------------------------------------- prep kernel
// Fragment-blocked transpose + tf32 round.
// Block (n8, sp): lane l=(g,tg) holds {w[k0][n], w[k0+1][n], w[k0+8][n],
// w[k0+9][n]} with n = n8*8+g, k0 = 16*sp + 2*tg.
__global__ void courier_prep(const float* __restrict__ w1, const float* __restrict__ w2) {
    int i = blockIdx.x * blockDim.x + threadIdx.x;
    if (i < 32 * SP1 * 32) {
        int n8 = i / (SP1 * 32);
        int rem = i % (SP1 * 32);
        int sp = rem >> 5, lane = rem & 31;
        int g = lane >> 2, tg = lane & 3;
        int n = n8 * 8 + g;
        int k0 = 16 * sp + 2 * tg;
        float4 v;
        v.x = __uint_as_float(f2tf32(w1[(k0)     * 256 + n]));
        v.y = __uint_as_float(f2tf32(w1[(k0 + 1) * 256 + n]));
        v.z = __uint_as_float(f2tf32(w1[(k0 + 8) * 256 + n]));
        v.w = __uint_as_float(f2tf32(w1[(k0 + 9) * 256 + n]));
        g_w1B[i] = v;
    }
    int j = i - 32 * SP1 * 32;
    if (j >= 0 && j < 32 * SP2 * 32) {
        int n8 = j / (SP2 * 32);
        int rem = j % (SP2 * 32);
        int sp = rem >> 5, lane = rem & 31;
        int g = lane >> 2, tg = lane & 3;
        int n = n8 * 8 + g;
        int k0 = 16 * sp + 2 * tg;
        float4 v;
        v.x = __uint_as_float(f2tf32(w2[(k0)     * 256 + n]));
        v.y = __uint_as_float(f2tf32(w2[(k0 + 1) * 256 + n]));
        v.z = __uint_as_float(f2tf32(w2[(k0 + 8) * 256 + n]));
        v.w = __uint_as_float(f2tf32(w2[(k0 + 9) * 256 + n]));
        g_w2B[j] = v;
    }
}

// ---------------------------------------------------------------- gemm core
// D[128,256] += A_packed * W_blocked. Warp tile 64x32 at (warp_m, warp_n).
template <int KS>
__device__ __forceinline__ void gemm_layer(const float4* __restrict__ Wb,
                                           const float4* __restrict__ smA4,
                                           int warp_m, int warp_n, int lane,
                                           float acc[4][4][4]) {
    constexpr int SP = KS / 2;
    const float4* bptr[4];
#pragma unroll
    for (int nf = 0; nf < 4; nf++)
        bptr[nf] = Wb + (size_t)((warp_n * 4 + nf) * SP) * 32 + lane;

    float4 bb[2][4];
#pragma unroll
    for (int nf = 0; nf < 4; nf++) bb[0][nf] = bptr[nf][0];

#pragma unroll 2
    for (int sp = 0; sp < SP; sp++) {
        const int cur = sp & 1;
        if (sp + 1 < SP) {
#pragma unroll
            for (int nf = 0; nf < 4; nf++)
                bb[cur ^ 1][nf] = bptr[nf][(sp + 1) * 32];
        }
#pragma unroll
        for (int h = 0; h < 2; h++) {
            const int s = 2 * sp + h;
            uint32_t a[4][4];
#pragma unroll
            for (int mf = 0; mf < 4; mf++) {
                float4 av = smA4[((warp_m * 4 + mf) * KS + s) * 32 + lane];
                a[mf][0] = __float_as_uint(av.x);
                a[mf][1] = __float_as_uint(av.y);
                a[mf][2] = __float_as_uint(av.z);
                a[mf][3] = __float_as_uint(av.w);
            }
#pragma unroll
            for (int mf = 0; mf < 4; mf++)
#pragma unroll
                for (int nf = 0; nf < 4; nf++) {
                    uint32_t b0 = __float_as_uint(h ? bb[cur][nf].z : bb[cur][nf].x);
                    uint32_t b1 = __float_as_uint(h ? bb[cur][nf].w : bb[cur][nf].y);
                    mma8(acc[mf][nf], a[mf], b0, b1);
                }
        }
    }
}

// ---------------------------------------------------------------- main kernel
__global__ __launch_bounds__(512, 1)
void courier_main(const float* __restrict__ xy, const float* __restrict__ tin,
                  const float* __restrict__ w_sx, const float* __restrict__ b_sx,
                  const float* __restrict__ w_cx, const float* __restrict__ b_cx,
                  const float* __restrict__ w_sy, const float* __restrict__ b_sy,
                  const float* __restrict__ w_cy, const float* __restrict__ b_cy,
                  const float* __restrict__ w_t,  const float* __restrict__ b_t,
                  const float* __restrict__ b1,   const float* __restrict__ b2,
                  float* __restrict__ out) {
    extern __shared__ float sm[];
    float*  smA  = sm + SM_A;
    float4* smA4 = (float4*)smA;
    float* sm_fr = sm + SM_FR;
    float* sm_wt = sm + SM_WT;
    float* sm_bt = sm + SM_BT;
    float* sm_b1 = sm + SM_B1;
    float* sm_b2 = sm + SM_B2;
    float* sm_x  = sm + SM_X;
    float* sm_y  = sm + SM_Y;
    float* sm_t  = sm + SM_T;

    const int tid    = threadIdx.x;
    const int lane   = tid & 31;
    const int wid    = tid >> 5;
    const int warp_m = wid >> 3;          // 0,1
    const int warp_n = wid & 7;           // 0..7

    // ---- stage small params + per-row inputs ----
    if (tid < 128) {
        int row = blockIdx.x * 128 + tid;
        float2 p = *(const float2*)(xy + 2 * row);
        sm_x[tid]  = p.x;
        sm_y[tid]  = p.y;
        sm_t[tid]  = tin[row];
        sm_wt[tid] = w_t[tid];
        sm_bt[tid] = b_t[tid];
    }
    if (tid < 64) {
        sm_fr[tid]       = w_sx[tid];  sm_fr[64 + tid]  = b_sx[tid];
        sm_fr[128 + tid] = w_cx[tid];  sm_fr[192 + tid] = b_cx[tid];
        sm_fr[256 + tid] = w_sy[tid];  sm_fr[320 + tid] = b_sy[tid];
        sm_fr[384 + tid] = w_cy[tid];  sm_fr[448 + tid] = b_cy[tid];
    }
    if (tid < 256) {
        sm_b1[tid] = b1[tid];
        sm_b2[tid] = b2[tid];
    }
    __syncthreads();

    // ---- generate embedding A1, packed layout, tf32-rounded ----
    {
        const int r  = tid >> 2;
        const int q4 = tid & 3;
        const float xv = sm_x[r];
        const float yv = sm_y[r];
        const float tv = sm_t[r];
        const int mtile = r >> 4, h = (r >> 3) & 1, g = r & 7;
        const int lanebase = g * 4;
#pragma unroll 8
        for (int j = 0; j < 96; j++) {
            int c = q4 * 96 + j;
            float v;
            if (c < 64) {
                v = __sinf(fmaf(xv, sm_fr[c], sm_fr[64 + c]));
            } else if (c < 128) {
                int i = c - 64;
                v = __cosf(fmaf(xv, sm_fr[128 + i], sm_fr[192 + i]));
            } else if (c < 192) {
                int i = c - 128;
                v = __sinf(fmaf(yv, sm_fr[256 + i], sm_fr[320 + i]));
            } else if (c < 256) {
                int i = c - 192;
                v = __cosf(fmaf(yv, sm_fr[384 + i], sm_fr[448 + i]));
            } else {
                int i = c - 256;
                v = lrelu(fmaf(tv, sm_wt[i], sm_bt[i]));
            }
            int s = c >> 3, o = c & 7, tq = o >> 1, hh = o & 1;
            smA[(((mtile * KS1 + s) * 32 + lanebase + tq) << 2) + h + 2 * hh] =
                __uint_as_float(f2tf32(v));
        }
    }
    __syncthreads();

    // ---- layer 1 ----
    float acc[4][4][4];
#pragma unroll
    for (int mf = 0; mf < 4; mf++)
#pragma unroll
        for (int nf = 0; nf < 4; nf++)
#pragma unroll
            for (int j = 0; j < 4; j++) acc[mf][nf][j] = 0.f;

    gemm_layer<KS1>(g_w1B, smA4, warp_m, warp_n, lane, acc);
    __syncthreads();   // all layer-1 A reads done before overwrite

    // ---- epilogue 1: bias + lrelu + tf32 -> packed A2, thread-local STS.128 ----
    {
        const int tg = lane & 3;
#pragma unroll
        for (int mf = 0; mf < 4; mf++) {
#pragma unroll
            for (int nf = 0; nf < 4; nf++) {
                int col = warp_n * 32 + nf * 8 + 2 * tg;
                float4 st;
                st.x = __uint_as_float(f2tf32(lrelu(acc[mf][nf][0] + sm_b1[col])));
                st.y = __uint_as_float(f2tf32(lrelu(acc[mf][nf][2] + sm_b1[col])));
                st.z = __uint_as_float(f2tf32(lrelu(acc[mf][nf][1] + sm_b1[col + 1])));
                st.w = __uint_as_float(f2tf32(lrelu(acc[mf][nf][3] + sm_b1[col + 1])));
                int s2 = warp_n * 4 + nf;                     // kstep in layer-2 space
                smA4[((warp_m * 4 + mf) * KS2 + s2) * 32 + lane] = st;
            }
        }
    }
    __syncthreads();

    // ---- layer 2 ----
#pragma unroll
    for (int mf = 0; mf < 4; mf++)
#pragma unroll
        for (int nf = 0; nf < 4; nf++)
#pragma unroll
            for (int j = 0; j < 4; j++) acc[mf][nf][j] = 0.f;

    gemm_layer<KS2>(g_w2B, smA4, warp_m, warp_n, lane, acc);

    // ---- final epilogue: bias + lrelu, float2 stores to gmem ----
    {
        const int g  = lane >> 2;
        const int tg = lane & 3;
        float* obase = out + (size_t)blockIdx.x * 128 * 256;
#pragma unroll
        for (int mf = 0; mf < 4; mf++) {
#pragma unroll
            for (int nf = 0; nf < 4; nf++) {
                int row = warp_m * 64 + mf * 16 + g;
                int col = warp_n * 32 + nf * 8 + 2 * tg;
                float2 v0, v1;
                v0.x = lrelu(acc[mf][nf][0] + sm_b2[col]);
                v0.y = lrelu(acc[mf][nf][1] + sm_b2[col + 1]);
                v1.x = lrelu(acc[mf][nf][2] + sm_b2[col]);
                v1.y = lrelu(acc[mf][nf][3] + sm_b2[col + 1]);
                *(float2*)(obase + row * 256 + col)       = v0;
                *(float2*)(obase + (row + 8) * 256 + col) = v1;
            }
        }
    }
}

// ---------------------------------------------------------------- launcher
extern "C" void kernel_launch(void* const* d_in, const int* in_sizes, int n_in,
                              void* d_out, int out_size) {
    const float* xy   = (const float*)d_in[0];
    const float* t    = (const float*)d_in[1];
    const float* w_sx = (const float*)d_in[2];
    const float* b_sx = (const float*)d_in[3];
    const float* w_cx = (const float*)d_in[4];
    const float* b_cx = (const float*)d_in[5];
    const float* w_sy = (const float*)d_in[6];
    const float* b_sy = (const float*)d_in[7];
    const float* w_cy = (const float*)d_in[8];
    const float* b_cy = (const float*)d_in[9];
    const float* w_t  = (const float*)d_in[10];
    const float* b_t  = (const float*)d_in[11];
    const float* w1   = (const float*)d_in[12];
    const float* b1   = (const float*)d_in[13];
    const float* w2   = (const float*)d_in[14];
    const float* b2   = (const float*)d_in[15];
    float* out = (float*)d_out;

    courier_prep<<<160, 256>>>(w1, w2);

    static bool attr_set = false;
    if (!attr_set) {
        cudaFuncSetAttribute(courier_main, cudaFuncAttributeMaxDynamicSharedMemorySize,
                             SMEM_BYTES);
        attr_set = true;
    }

    courier_main<<<2048, 512, SMEM_BYTES>>>(xy, t, w_sx, b_sx, w_cx, b_cx,
                                            w_sy, b_sy, w_cy, b_cy,
                                            w_t, b_t, b1, b2, out);
}

// round 6
// speedup vs baseline: 2.2418x; 1.6928x over previous
#include <cuda_runtime.h>
#include <cuda_fp16.h>
#include <cstdint>

// ============================================================================
// CourierEncoder fused MLP, sm_103 plain-target mma.sync FP16 path, round 6.
//   emb[B,384] -> h1 = lrelu(emb@w1+b1) -> out = lrelu(h1@w2+b2)
// fp16 operands (11-bit significand == tf32), fp32 accumulate, m16n8k16.
// CTA = 128 rows, 512 threads = 16 warps in 2(M64) x 8(N32) grid.
// Warp tile 64x32: mf=4, nf=4, 64 f32 accs/lane.
// A: fragment-major packed fp16 smem -> one LDS.128 per (mf, kstep) per warp.
// B: fragment-blocked fp16 gmem -> one LDG.128 per (nf, kstep-PAIR) per warp.
// ============================================================================

static constexpr float NEG_SLOPEF = 0.01f;
static constexpr int KS1 = 24;   // 384/16 k-steps, layer 1
static constexpr int KS2 = 16;   // 256/16 k-steps, layer 2
static constexpr int SP1 = KS1 / 2;
static constexpr int SP2 = KS2 / 2;

// fragment-blocked fp16 weights: [n8][sp][lane] uint4 = {b0(2sp),b1(2sp),b0(2sp+1),b1(2sp+1)}
__device__ uint4 g_w1B[32 * SP1 * 32];
__device__ uint4 g_w2B[32 * SP2 * 32];

// ---- smem layout (f32 words) ----
// A packed fp16: 8 mtiles * KS1 * 32 lanes * uint4 = 6144 uint4 = 24576 words
static constexpr int SM_A    = 0;
static constexpr int SM_FR   = 24576;
static constexpr int SM_WT   = SM_FR + 512;
static constexpr int SM_BT   = SM_WT + 128;
static constexpr int SM_B1   = SM_BT + 128;
static constexpr int SM_B2   = SM_B1 + 256;
static constexpr int SM_X    = SM_B2 + 256;
static constexpr int SM_Y    = SM_X + 128;
static constexpr int SM_T    = SM_Y + 128;
static constexpr int SMEM_WORDS = SM_T + 128;
static constexpr int SMEM_BYTES = SMEM_WORDS * 4;   // ~105 KB

__device__ __forceinline__ float lrelu(float v) { return v >= 0.f ? v : NEG_SLOPEF * v; }

__device__ __forceinline__ void mma16(float* c, const uint32_t* a, uint32_t b0, uint32_t b1) {
    asm volatile(
        "mma.sync.aligned.m16n8k16.row.col.f32.f16.f16.f32 "
        "{%0,%1,%2,%3}, {%4,%5,%6,%7}, {%8,%9}, {%0,%1,%2,%3};"
        : "+f"(c[0]), "+f"(c[1]), "+f"(c[2]), "+f"(c[3])
        : "r"(a[0]), "r"(a[1]), "r"(a[2]), "r"(a[3]), "r"(b0), "r"(b1));
}

__device__ __forceinline__ uint32_t pack2(float lo, float hi) {
    __half2 h = __floats2half2_rn(lo, hi);
    return *(uint32_t*)&h;
}

// ---------------------------------------------------------------- prep kernel
// Fragment-blocked fp16 transpose. Block (n8, sp), lane (g,tg), n = n8*8+g:
//  b0(s) = {w[16s+2tg][n], w[16s+2tg+1][n]},  b1(s) = {w[16s+8+2tg][n], w[16s+9+2tg][n]}
//  uint4 = {b0(2sp), b1(2sp), b0(2sp+1), b1(2sp+1)}
__global__ void courier_prep(const float* __restrict__ w1, const float* __restrict__ w2) {
    int i = blockIdx.x * blockDim.x + threadIdx.x;
    if (i < 32 * SP1 * 32) {
        int n8 = i / (SP1 * 32);
        int rem = i % (SP1 * 32);
        int sp = rem >> 5, lane = rem & 31;
        int g = lane >> 2, tg = lane & 3;
        int n = n8 * 8 + g;
        int k0 = 32 * sp + 2 * tg;          // s = 2sp
        int k1 = k0 + 16;                   // s = 2sp+1
        uint4 v;
        v.x = pack2(w1[(k0)      * 256 + n], w1[(k0 + 1)  * 256 + n]);
        v.y = pack2(w1[(k0 + 8)  * 256 + n], w1[(k0 + 9)  * 256 + n]);
        v.z = pack2(w1[(k1)      * 256 + n], w1[(k1 + 1)  * 256 + n]);
        v.w = pack2(w1[(k1 + 8)  * 256 + n], w1[(k1 + 9)  * 256 + n]);
        g_w1B[i] = v;
    }
    int j = i - 32 * SP1 * 32;
    if (j >= 0 && j < 32 * SP2 * 32) {
        int n8 = j / (SP2 * 32);
        int rem = j % (SP2 * 32);
        int sp = rem >> 5, lane = rem & 31;
        int g = lane >> 2, tg = lane & 3;
        int n = n8 * 8 + g;
        int k0 = 32 * sp + 2 * tg;
        int k1 = k0 + 16;
        uint4 v;
        v.x = pack2(w2[(k0)      * 256 + n], w2[(k0 + 1)  * 256 + n]);
        v.y = pack2(w2[(k0 + 8)  * 256 + n], w2[(k0 + 9)  * 256 + n]);
        v.z = pack2(w2[(k1)      * 256 + n], w2[(k1 + 1)  * 256 + n]);
        v.w = pack2(w2[(k1 + 8)  * 256 + n], w2[(k1 + 9)  * 256 + n]);
        g_w2B[j] = v;
    }
}

// ---------------------------------------------------------------- gemm core
template <int KS>
__device__ __forceinline__ void gemm_layer(const uint4* __restrict__ Wb,
                                           const uint4* __restrict__ smA4,
                                           int warp_m, int warp_n, int lane,
                                           float acc[4][4][4]) {
    constexpr int SP = KS / 2;
    const uint4* bptr[4];
#pragma unroll
    for (int nf = 0; nf < 4; nf++)
        bptr[nf] = Wb + (size_t)((warp_n * 4 + nf) * SP) * 32 + lane;

    uint4 bb[2][4];
#pragma unroll
    for (int nf = 0; nf < 4; nf++) bb[0][nf] = bptr[nf][0];

#pragma unroll 2
    for (int sp = 0; sp < SP; sp++) {
        const int cur = sp & 1;
        if (sp + 1 < SP) {
#pragma unroll
            for (int nf = 0; nf < 4; nf++)
                bb[cur ^ 1][nf] = bptr[nf][(sp + 1) * 32];
        }
#pragma unroll
        for (int h = 0; h < 2; h++) {
            const int s = 2 * sp + h;
            uint32_t a[4][4];
#pragma unroll
            for (int mf = 0; mf < 4; mf++) {
                uint4 av = smA4[((warp_m * 4 + mf) * KS + s) * 32 + lane];
                a[mf][0] = av.x; a[mf][1] = av.y; a[mf][2] = av.z; a[mf][3] = av.w;
            }
#pragma unroll
            for (int mf = 0; mf < 4; mf++)
#pragma unroll
                for (int nf = 0; nf < 4; nf++) {
                    uint32_t b0 = h ? bb[cur][nf].z : bb[cur][nf].x;
                    uint32_t b1 = h ? bb[cur][nf].w : bb[cur][nf].y;
                    mma16(acc[mf][nf], a[mf], b0, b1);
                }
        }
    }
}

// ---------------------------------------------------------------- main kernel
__global__ __launch_bounds__(512, 1)
void courier_main(const float* __restrict__ xy, const float* __restrict__ tin,
                  const float* __restrict__ w_sx, const float* __restrict__ b_sx,
                  const float* __restrict__ w_cx, const float* __restrict__ b_cx,
                  const float* __restrict__ w_sy, const float* __restrict__ b_sy,
                  const float* __restrict__ w_cy, const float* __restrict__ b_cy,
                  const float* __restrict__ w_t,  const float* __restrict__ b_t,
                  const float* __restrict__ b1,   const float* __restrict__ b2,
                  float* __restrict__ out) {
    extern __shared__ float sm[];
    uint4*  smA4 = (uint4*)sm;          // packed fp16 A fragments
    __half* smAh = (__half*)sm;
    float* sm_fr = sm + SM_FR;
    float* sm_wt = sm + SM_WT;
    float* sm_bt = sm + SM_BT;
    float* sm_b1 = sm + SM_B1;
    float* sm_b2 = sm + SM_B2;
    float* sm_x  = sm + SM_X;
    float* sm_y  = sm + SM_Y;
    float* sm_t  = sm + SM_T;

    const int tid    = threadIdx.x;
    const int lane   = tid & 31;
    const int wid    = tid >> 5;
    const int warp_m = wid >> 3;          // 0,1
    const int warp_n = wid & 7;           // 0..7

    // ---- stage small params + per-row inputs ----
    if (tid < 128) {
        int row = blockIdx.x * 128 + tid;
        float2 p = *(const float2*)(xy + 2 * row);
        sm_x[tid]  = p.x;
        sm_y[tid]  = p.y;
        sm_t[tid]  = tin[row];
        sm_wt[tid] = w_t[tid];
        sm_bt[tid] = b_t[tid];
    }
    if (tid < 64) {
        sm_fr[tid]       = w_sx[tid];  sm_fr[64 + tid]  = b_sx[tid];
        sm_fr[128 + tid] = w_cx[tid];  sm_fr[192 + tid] = b_cx[tid];
        sm_fr[256 + tid] = w_sy[tid];  sm_fr[320 + tid] = b_sy[tid];
        sm_fr[384 + tid] = w_cy[tid];  sm_fr[448 + tid] = b_cy[tid];
    }
    if (tid < 256) {
        sm_b1[tid] = b1[tid];
        sm_b2[tid] = b2[tid];
    }
    __syncthreads();

    // ---- generate embedding A1, packed fp16 layout ----
    // thread = (row r, quarter q4); handles 48 col-PAIRS (one half2 store each)
    // value (r, c): mt=r>>4, g=r&7, hi=(r>>3)&1; s=c>>4, o=c&15, half=o>>3,
    //   tg=(o&7)>>1, word=hi+2*half; fp16 idx = (frag*32 + g*4+tg)*8 + word*2 + (o&1)
    {
        const int r  = tid >> 2;
        const int q4 = tid & 3;
        const float xv = sm_x[r];
        const float yv = sm_y[r];
        const float tv = sm_t[r];
        const int mt = r >> 4, hi = (r >> 3) & 1, g = r & 7;

        auto embval = [&](int c) -> float {
            if (c < 64)  return __sinf(fmaf(xv, sm_fr[c], sm_fr[64 + c]));
            if (c < 128) { int i = c - 64;  return __cosf(fmaf(xv, sm_fr[128 + i], sm_fr[192 + i])); }
            if (c < 192) { int i = c - 128; return __sinf(fmaf(yv, sm_fr[256 + i], sm_fr[320 + i])); }
            if (c < 256) { int i = c - 192; return __cosf(fmaf(yv, sm_fr[384 + i], sm_fr[448 + i])); }
            int i = c - 256; return lrelu(fmaf(tv, sm_wt[i], sm_bt[i]));
        };

#pragma unroll 4
        for (int j = 0; j < 48; j++) {
            int c = (q4 * 48 + j) * 2;
            float v0 = embval(c);
            float v1 = embval(c + 1);
            int s = c >> 4, o = c & 15;
            int half = o >> 3, tg = (o & 7) >> 1;
            int word = hi + 2 * half;
            int idx = (((mt * KS1 + s) * 32 + g * 4 + tg) << 3) + word * 2;
            *(__half2*)(smAh + idx) = __floats2half2_rn(v0, v1);
        }
    }
    __syncthreads();

    // ---- layer 1 ----
    float acc[4][4][4];
#pragma unroll
    for (int mf = 0; mf < 4; mf++)
#pragma unroll
        for (int nf = 0; nf < 4; nf++)
#pragma unroll
            for (int j = 0; j < 4; j++) acc[mf][nf][j] = 0.f;

    gemm_layer<KS1>(g_w1B, smA4, warp_m, warp_n, lane, acc);
    __syncthreads();   // all layer-1 A reads done before overwrite

    // ---- epilogue 1: bias + lrelu + fp16 -> packed A2, thread-local STS.128 ----
    // (mf, e): nf=2e -> words 0,1 ; nf=2e+1 -> words 2,3 of frag
    // (warp_m*4+mf, s2=warp_n*2+e)
    {
        const int tg = lane & 3;
#pragma unroll
        for (int mf = 0; mf < 4; mf++) {
#pragma unroll
            for (int e = 0; e < 2; e++) {
                int col0 = warp_n * 32 + (2 * e) * 8 + 2 * tg;
                int col1 = col0 + 8;
                uint4 st;
                st.x = pack2(lrelu(acc[mf][2*e][0]   + sm_b1[col0]),
                             lrelu(acc[mf][2*e][1]   + sm_b1[col0 + 1]));
                st.y = pack2(lrelu(acc[mf][2*e][2]   + sm_b1[col0]),
                             lrelu(acc[mf][2*e][3]   + sm_b1[col0 + 1]));
                st.z = pack2(lrelu(acc[mf][2*e+1][0] + sm_b1[col1]),
                             lrelu(acc[mf][2*e+1][1] + sm_b1[col1 + 1]));
                st.w = pack2(lrelu(acc[mf][2*e+1][2] + sm_b1[col1]),
                             lrelu(acc[mf][2*e+1][3] + sm_b1[col1 + 1]));
                int s2 = warp_n * 2 + e;
                smA4[((warp_m * 4 + mf) * KS2 + s2) * 32 + lane] = st;
            }
        }
    }
    __syncthreads();

    // ---- layer 2 ----
#pragma unroll
    for (int mf = 0; mf < 4; mf++)
#pragma unroll
        for (int nf = 0; nf < 4; nf++)
#pragma unroll
            for (int j = 0; j < 4; j++) acc[mf][nf][j] = 0.f;

    gemm_layer<KS2>(g_w2B, smA4, warp_m, warp_n, lane, acc);

    // ---- final epilogue: bias + lrelu, float2 stores to gmem ----
    {
        const int g  = lane >> 2;
        const int tg = lane & 3;
        float* obase = out + (size_t)blockIdx.x * 128 * 256;
#pragma unroll
        for (int mf = 0; mf < 4; mf++) {
#pragma unroll
            for (int nf = 0; nf < 4; nf++) {
                int row = warp_m * 64 + mf * 16 + g;
                int col = warp_n * 32 + nf * 8 + 2 * tg;
                float2 v0, v1;
                v0.x = lrelu(acc[mf][nf][0] + sm_b2[col]);
                v0.y = lrelu(acc[mf][nf][1] + sm_b2[col + 1]);
                v1.x = lrelu(acc[mf][nf][2] + sm_b2[col]);
                v1.y = lrelu(acc[mf][nf][3] + sm_b2[col + 1]);
                *(float2*)(obase + row * 256 + col)       = v0;
                *(float2*)(obase + (row + 8) * 256 + col) = v1;
            }
        }
    }
}

// ---------------------------------------------------------------- launcher
extern "C" void kernel_launch(void* const* d_in, const int* in_sizes, int n_in,
                              void* d_out, int out_size) {
    const float* xy   = (const float*)d_in[0];
    const float* t    = (const float*)d_in[1];
    const float* w_sx = (const float*)d_in[2];
    const float* b_sx = (const float*)d_in[3];
    const float* w_cx = (const float*)d_in[4];
    const float* b_cx = (const float*)d_in[5];
    const float* w_sy = (const float*)d_in[6];
    const float* b_sy = (const float*)d_in[7];
    const float* w_cy = (const float*)d_in[8];
    const float* b_cy = (const float*)d_in[9];
    const float* w_t  = (const float*)d_in[10];
    const float* b_t  = (const float*)d_in[11];
    const float* w1   = (const float*)d_in[12];
    const float* b1   = (const float*)d_in[13];
    const float* w2   = (const float*)d_in[14];
    const float* b2   = (const float*)d_in[15];
    float* out = (float*)d_out;

    courier_prep<<<80, 256>>>(w1, w2);

    static bool attr_set = false;
    if (!attr_set) {
        cudaFuncSetAttribute(courier_main, cudaFuncAttributeMaxDynamicSharedMemorySize,
                             SMEM_BYTES);
        attr_set = true;
    }

    courier_main<<<2048, 512, SMEM_BYTES>>>(xy, t, w_sx, b_sx, w_cx, b_cx,
                                            w_sy, b_sy, w_cy, b_cy,
                                            w_t, b_t, b1, b2, out);
}

// round 7
// speedup vs baseline: 2.6153x; 1.1666x over previous
#include <cuda_runtime.h>
#include <cuda_fp16.h>
#include <cstdint>

// ============================================================================
// CourierEncoder fused MLP, sm_103 plain-target mma.sync FP16 path, round 7.
//   emb[B,384] -> h1 = lrelu(emb@w1+b1) -> out = lrelu(h1@w2+b2)
// fp16 operands (11-bit significand == tf32), fp32 accumulate, m16n8k16.
// CTA = 64 rows, 256 threads = 8 warps in 1(M64) x 8(N32) grid; 2 CTAs/SM
// co-resident for phase overlap. Warp tile 64x32: mf=4, nf=4, 64 accs/lane.
// A1 (emb) and A2 (h1) in SEPARATE packed fp16 smem buffers (drops the WAR
// barrier after gemm1). One LDS.128 per (mf, kstep); one LDG.128 per
// (nf, kstep-pair) from fragment-blocked gmem weights.
// ============================================================================

static constexpr float NEG_SLOPEF = 0.01f;
static constexpr int KS1 = 24;   // 384/16 k-steps, layer 1
static constexpr int KS2 = 16;   // 256/16 k-steps, layer 2
static constexpr int SP1 = KS1 / 2;
static constexpr int SP2 = KS2 / 2;

// fragment-blocked fp16 weights: [n8][sp][lane] uint4 = {b0(2sp),b1(2sp),b0(2sp+1),b1(2sp+1)}
__device__ uint4 g_w1B[32 * SP1 * 32];
__device__ uint4 g_w2B[32 * SP2 * 32];

// ---- smem layout (f32 words) ----
// A1 packed fp16: 4 mtiles * KS1 * 32 lanes * uint4 = 3072 uint4 = 12288 words
// A2 packed fp16: 4 mtiles * KS2 * 32 lanes * uint4 = 2048 uint4 =  8192 words
static constexpr int SM_A1   = 0;
static constexpr int SM_A2   = 12288;
static constexpr int SM_FR   = 20480;
static constexpr int SM_WT   = SM_FR + 512;
static constexpr int SM_BT   = SM_WT + 128;
static constexpr int SM_B1   = SM_BT + 128;
static constexpr int SM_B2   = SM_B1 + 256;
static constexpr int SM_X    = SM_B2 + 256;
static constexpr int SM_Y    = SM_X + 64;
static constexpr int SM_T    = SM_Y + 64;
static constexpr int SMEM_WORDS = SM_T + 64;
static constexpr int SMEM_BYTES = SMEM_WORDS * 4;   // ~86 KB -> 2 CTAs/SM

__device__ __forceinline__ float lrelu(float v) { return v >= 0.f ? v : NEG_SLOPEF * v; }

__device__ __forceinline__ void mma16(float* c, const uint32_t* a, uint32_t b0, uint32_t b1) {
    asm volatile(
        "mma.sync.aligned.m16n8k16.row.col.f32.f16.f16.f32 "
        "{%0,%1,%2,%3}, {%4,%5,%6,%7}, {%8,%9}, {%0,%1,%2,%3};"
        : "+f"(c[0]), "+f"(c[1]), "+f"(c[2]), "+f"(c[3])
        : "r"(a[0]), "r"(a[1]), "r"(a[2]), "r"(a[3]), "r"(b0), "r"(b1));
}

__device__ __forceinline__ uint32_t pack2(float lo, float hi) {
    __half2 h = __floats2half2_rn(lo, hi);
    return *(uint32_t*)&h;
}

// ---------------------------------------------------------------- prep kernel
// Fragment-blocked fp16 transpose. Block (n8, sp), lane (g,tg), n = n8*8+g:
//  b0(s) = {w[16s+2tg][n], w[16s+2tg+1][n]},  b1(s) = {w[16s+8+2tg][n], w[16s+9+2tg][n]}
__global__ void courier_prep(const float* __restrict__ w1, const float* __restrict__ w2) {
    int i = blockIdx.x * blockDim.x + threadIdx.x;
    if (i < 32 * SP1 * 32) {
        int n8 = i / (SP1 * 32);
        int rem = i % (SP1 * 32);
        int sp = rem >> 5, lane = rem & 31;
        int g = lane >> 2, tg = lane & 3;
        int n = n8 * 8 + g;
        int k0 = 32 * sp + 2 * tg;
        int k1 = k0 + 16;
        uint4 v;
        v.x = pack2(w1[(k0)      * 256 + n], w1[(k0 + 1)  * 256 + n]);
        v.y = pack2(w1[(k0 + 8)  * 256 + n], w1[(k0 + 9)  * 256 + n]);
        v.z = pack2(w1[(k1)      * 256 + n], w1[(k1 + 1)  * 256 + n]);
        v.w = pack2(w1[(k1 + 8)  * 256 + n], w1[(k1 + 9)  * 256 + n]);
        g_w1B[i] = v;
    }
    int j = i - 32 * SP1 * 32;
    if (j >= 0 && j < 32 * SP2 * 32) {
        int n8 = j / (SP2 * 32);
        int rem = j % (SP2 * 32);
        int sp = rem >> 5, lane = rem & 31;
        int g = lane >> 2, tg = lane & 3;
        int n = n8 * 8 + g;
        int k0 = 32 * sp + 2 * tg;
        int k1 = k0 + 16;
        uint4 v;
        v.x = pack2(w2[(k0)      * 256 + n], w2[(k0 + 1)  * 256 + n]);
        v.y = pack2(w2[(k0 + 8)  * 256 + n], w2[(k0 + 9)  * 256 + n]);
        v.z = pack2(w2[(k1)      * 256 + n], w2[(k1 + 1)  * 256 + n]);
        v.w = pack2(w2[(k1 + 8)  * 256 + n], w2[(k1 + 9)  * 256 + n]);
        g_w2B[j] = v;
    }
}

// ---------------------------------------------------------------- gemm core
// D[64,256] += A_packed * W_blocked. Warp tile 64x32 at warp_n (mf spans all rows).
template <int KS>
__device__ __forceinline__ void gemm_layer(const uint4* __restrict__ Wb,
                                           const uint4* __restrict__ smA4,
                                           int warp_n, int lane,
                                           float acc[4][4][4]) {
    constexpr int SP = KS / 2;
    const uint4* bptr[4];
#pragma unroll
    for (int nf = 0; nf < 4; nf++)
        bptr[nf] = Wb + (size_t)((warp_n * 4 + nf) * SP) * 32 + lane;

    uint4 bb[2][4];
#pragma unroll
    for (int nf = 0; nf < 4; nf++) bb[0][nf] = bptr[nf][0];

#pragma unroll 2
    for (int sp = 0; sp < SP; sp++) {
        const int cur = sp & 1;
        if (sp + 1 < SP) {
#pragma unroll
            for (int nf = 0; nf < 4; nf++)
                bb[cur ^ 1][nf] = bptr[nf][(sp + 1) * 32];
        }
#pragma unroll
        for (int h = 0; h < 2; h++) {
            const int s = 2 * sp + h;
            uint32_t a[4][4];
#pragma unroll
            for (int mf = 0; mf < 4; mf++) {
                uint4 av = smA4[(mf * KS + s) * 32 + lane];
                a[mf][0] = av.x; a[mf][1] = av.y; a[mf][2] = av.z; a[mf][3] = av.w;
            }
#pragma unroll
            for (int mf = 0; mf < 4; mf++)
#pragma unroll
                for (int nf = 0; nf < 4; nf++) {
                    uint32_t b0 = h ? bb[cur][nf].z : bb[cur][nf].x;
                    uint32_t b1 = h ? bb[cur][nf].w : bb[cur][nf].y;
                    mma16(acc[mf][nf], a[mf], b0, b1);
                }
        }
    }
}

// ---------------------------------------------------------------- main kernel
__global__ __launch_bounds__(256, 2)
void courier_main(const float* __restrict__ xy, const float* __restrict__ tin,
                  const float* __restrict__ w_sx, const float* __restrict__ b_sx,
                  const float* __restrict__ w_cx, const float* __restrict__ b_cx,
                  const float* __restrict__ w_sy, const float* __restrict__ b_sy,
                  const float* __restrict__ w_cy, const float* __restrict__ b_cy,
                  const float* __restrict__ w_t,  const float* __restrict__ b_t,
                  const float* __restrict__ b1,   const float* __restrict__ b2,
                  float* __restrict__ out) {
    extern __shared__ float sm[];
    uint4*  smA1 = (uint4*)(sm + SM_A1);
    uint4*  smA2 = (uint4*)(sm + SM_A2);
    __half* smA1h = (__half*)(sm + SM_A1);
    float* sm_fr = sm + SM_FR;
    float* sm_wt = sm + SM_WT;
    float* sm_bt = sm + SM_BT;
    float* sm_b1 = sm + SM_B1;
    float* sm_b2 = sm + SM_B2;
    float* sm_x  = sm + SM_X;
    float* sm_y  = sm + SM_Y;
    float* sm_t  = sm + SM_T;

    const int tid    = threadIdx.x;
    const int lane   = tid & 31;
    const int warp_n = tid >> 5;          // 0..7

    // ---- stage small params + per-row inputs ----
    if (tid < 64) {
        int row = blockIdx.x * 64 + tid;
        float2 p = *(const float2*)(xy + 2 * row);
        sm_x[tid] = p.x;
        sm_y[tid] = p.y;
        sm_t[tid] = tin[row];
    }
    if (tid < 128) {
        sm_wt[tid] = w_t[tid];
        sm_bt[tid] = b_t[tid];
    }
    if (tid < 64) {
        sm_fr[tid]       = w_sx[tid];  sm_fr[64 + tid]  = b_sx[tid];
        sm_fr[128 + tid] = w_cx[tid];  sm_fr[192 + tid] = b_cx[tid];
        sm_fr[256 + tid] = w_sy[tid];  sm_fr[320 + tid] = b_sy[tid];
        sm_fr[384 + tid] = w_cy[tid];  sm_fr[448 + tid] = b_cy[tid];
    }
    sm_b1[tid] = b1[tid];
    sm_b2[tid] = b2[tid];
    __syncthreads();

    // ---- generate embedding A1 [64 x 384], packed fp16 layout ----
    // thread = (row r, quarter q4); 48 half2 stores each.
    {
        const int r  = tid >> 2;          // 0..63
        const int q4 = tid & 3;
        const float xv = sm_x[r];
        const float yv = sm_y[r];
        const float tv = sm_t[r];
        const int mt = r >> 4, hi = (r >> 3) & 1, g = r & 7;

        auto embval = [&](int c) -> float {
            if (c < 64)  return __sinf(fmaf(xv, sm_fr[c], sm_fr[64 + c]));
            if (c < 128) { int i = c - 64;  return __cosf(fmaf(xv, sm_fr[128 + i], sm_fr[192 + i])); }
            if (c < 192) { int i = c - 128; return __sinf(fmaf(yv, sm_fr[256 + i], sm_fr[320 + i])); }
            if (c < 256) { int i = c - 192; return __cosf(fmaf(yv, sm_fr[384 + i], sm_fr[448 + i])); }
            int i = c - 256; return lrelu(fmaf(tv, sm_wt[i], sm_bt[i]));
        };

#pragma unroll 4
        for (int j = 0; j < 48; j++) {
            int c = (q4 * 48 + j) * 2;
            float v0 = embval(c);
            float v1 = embval(c + 1);
            int s = c >> 4, o = c & 15;
            int half = o >> 3, tg = (o & 7) >> 1;
            int word = hi + 2 * half;
            int idx = (((mt * KS1 + s) * 32 + g * 4 + tg) << 3) + word * 2;
            *(__half2*)(smA1h + idx) = __floats2half2_rn(v0, v1);
        }
    }
    __syncthreads();

    // ---- layer 1 ----
    float acc[4][4][4];
#pragma unroll
    for (int mf = 0; mf < 4; mf++)
#pragma unroll
        for (int nf = 0; nf < 4; nf++)
#pragma unroll
            for (int j = 0; j < 4; j++) acc[mf][nf][j] = 0.f;

    gemm_layer<KS1>(g_w1B, smA1, warp_n, lane, acc);

    // ---- epilogue 1: bias + lrelu + fp16 -> A2 (separate buffer, no WAR sync) ----
    {
        const int tg = lane & 3;
#pragma unroll
        for (int mf = 0; mf < 4; mf++) {
#pragma unroll
            for (int e = 0; e < 2; e++) {
                int col0 = warp_n * 32 + (2 * e) * 8 + 2 * tg;
                int col1 = col0 + 8;
                uint4 st;
                st.x = pack2(lrelu(acc[mf][2*e][0]   + sm_b1[col0]),
                             lrelu(acc[mf][2*e][1]   + sm_b1[col0 + 1]));
                st.y = pack2(lrelu(acc[mf][2*e][2]   + sm_b1[col0]),
                             lrelu(acc[mf][2*e][3]   + sm_b1[col0 + 1]));
                st.z = pack2(lrelu(acc[mf][2*e+1][0] + sm_b1[col1]),
                             lrelu(acc[mf][2*e+1][1] + sm_b1[col1 + 1]));
                st.w = pack2(lrelu(acc[mf][2*e+1][2] + sm_b1[col1]),
                             lrelu(acc[mf][2*e+1][3] + sm_b1[col1 + 1]));
                int s2 = warp_n * 2 + e;
                smA2[(mf * KS2 + s2) * 32 + lane] = st;
            }
        }
    }
    __syncthreads();

    // ---- layer 2 ----
#pragma unroll
    for (int mf = 0; mf < 4; mf++)
#pragma unroll
        for (int nf = 0; nf < 4; nf++)
#pragma unroll
            for (int j = 0; j < 4; j++) acc[mf][nf][j] = 0.f;

    gemm_layer<KS2>(g_w2B, smA2, warp_n, lane, acc);

    // ---- final epilogue: bias + lrelu, float2 stores to gmem ----
    {
        const int g  = lane >> 2;
        const int tg = lane & 3;
        float* obase = out + (size_t)blockIdx.x * 64 * 256;
#pragma unroll
        for (int mf = 0; mf < 4; mf++) {
#pragma unroll
            for (int nf = 0; nf < 4; nf++) {
                int row = mf * 16 + g;
                int col = warp_n * 32 + nf * 8 + 2 * tg;
                float2 v0, v1;
                v0.x = lrelu(acc[mf][nf][0] + sm_b2[col]);
                v0.y = lrelu(acc[mf][nf][1] + sm_b2[col + 1]);
                v1.x = lrelu(acc[mf][nf][2] + sm_b2[col]);
                v1.y = lrelu(acc[mf][nf][3] + sm_b2[col + 1]);
                *(float2*)(obase + row * 256 + col)       = v0;
                *(float2*)(obase + (row + 8) * 256 + col) = v1;
            }
        }
    }
}

// ---------------------------------------------------------------- launcher
extern "C" void kernel_launch(void* const* d_in, const int* in_sizes, int n_in,
                              void* d_out, int out_size) {
    const float* xy   = (const float*)d_in[0];
    const float* t    = (const float*)d_in[1];
    const float* w_sx = (const float*)d_in[2];
    const float* b_sx = (const float*)d_in[3];
    const float* w_cx = (const float*)d_in[4];
    const float* b_cx = (const float*)d_in[5];
    const float* w_sy = (const float*)d_in[6];
    const float* b_sy = (const float*)d_in[7];
    const float* w_cy = (const float*)d_in[8];
    const float* b_cy = (const float*)d_in[9];
    const float* w_t  = (const float*)d_in[10];
    const float* b_t  = (const float*)d_in[11];
    const float* w1   = (const float*)d_in[12];
    const float* b1   = (const float*)d_in[13];
    const float* w2   = (const float*)d_in[14];
    const float* b2   = (const float*)d_in[15];
    float* out = (float*)d_out;

    courier_prep<<<80, 256>>>(w1, w2);

    static bool attr_set = false;
    if (!attr_set) {
        cudaFuncSetAttribute(courier_main, cudaFuncAttributeMaxDynamicSharedMemorySize,
                             SMEM_BYTES);
        attr_set = true;
    }

    courier_main<<<4096, 256, SMEM_BYTES>>>(xy, t, w_sx, b_sx, w_cx, b_cx,
                                            w_sy, b_sy, w_cy, b_cy,
                                            w_t, b_t, b1, b2, out);
}

// round 8
// speedup vs baseline: 4.1182x; 1.5747x over previous
#include <cuda_runtime.h>
#include <cuda_fp16.h>
#include <cstdint>

// ============================================================================
// CourierEncoder fused MLP, sm_103 plain-target mma.sync FP16 path, round 8.
//   emb[B,384] -> h1 = lrelu(emb@w1+b1) -> out = lrelu(h1@w2+b2)
// fp16 operands (11-bit significand == tf32), fp32 accumulate, m16n8k16.
// CTA = 64 rows, 256 threads = 8 warps in 1(M64) x 8(N32) grid; 2 CTAs/SM.
// Warp tile 64x32: mf=4, nf=4, 64 accs/lane.
// A1/A2 in separate packed fp16 smem buffers; emb is generated FRAGMENT-
// NATIVE: each thread produces one whole uint4 fragment element per step ->
// thread-local coalesced STS.128 (no scattered half2 stores).
// One LDS.128 per (mf, kstep); one LDG.128 per (nf, kstep-pair), fully
// unrolled so ptxas can batch LDGs for MLP.
// ============================================================================

static constexpr float NEG_SLOPEF = 0.01f;
static constexpr int KS1 = 24;   // 384/16 k-steps, layer 1
static constexpr int KS2 = 16;   // 256/16 k-steps, layer 2
static constexpr int SP1 = KS1 / 2;
static constexpr int SP2 = KS2 / 2;

// fragment-blocked fp16 weights: [n8][sp][lane] uint4 = {b0(2sp),b1(2sp),b0(2sp+1),b1(2sp+1)}
__device__ uint4 g_w1B[32 * SP1 * 32];
__device__ uint4 g_w2B[32 * SP2 * 32];

// ---- smem layout (f32 words) ----
static constexpr int SM_A1   = 0;            // 3072 uint4 = 12288 words
static constexpr int SM_A2   = 12288;        // 2048 uint4 =  8192 words
static constexpr int SM_FR   = 20480;
static constexpr int SM_WT   = SM_FR + 512;
static constexpr int SM_BT   = SM_WT + 128;
static constexpr int SM_B1   = SM_BT + 128;
static constexpr int SM_B2   = SM_B1 + 256;
static constexpr int SM_X    = SM_B2 + 256;
static constexpr int SM_Y    = SM_X + 64;
static constexpr int SM_T    = SM_Y + 64;
static constexpr int SMEM_WORDS = SM_T + 64;
static constexpr int SMEM_BYTES = SMEM_WORDS * 4;   // ~86 KB -> 2 CTAs/SM

__device__ __forceinline__ float lrelu(float v) { return v >= 0.f ? v : NEG_SLOPEF * v; }

__device__ __forceinline__ void mma16(float* c, const uint32_t* a, uint32_t b0, uint32_t b1) {
    asm volatile(
        "mma.sync.aligned.m16n8k16.row.col.f32.f16.f16.f32 "
        "{%0,%1,%2,%3}, {%4,%5,%6,%7}, {%8,%9}, {%0,%1,%2,%3};"
        : "+f"(c[0]), "+f"(c[1]), "+f"(c[2]), "+f"(c[3])
        : "r"(a[0]), "r"(a[1]), "r"(a[2]), "r"(a[3]), "r"(b0), "r"(b1));
}

__device__ __forceinline__ uint32_t pack2(float lo, float hi) {
    __half2 h = __floats2half2_rn(lo, hi);
    return *(uint32_t*)&h;
}

// ---------------------------------------------------------------- prep kernel
__global__ void courier_prep(const float* __restrict__ w1, const float* __restrict__ w2) {
    int i = blockIdx.x * blockDim.x + threadIdx.x;
    if (i < 32 * SP1 * 32) {
        int n8 = i / (SP1 * 32);
        int rem = i % (SP1 * 32);
        int sp = rem >> 5, lane = rem & 31;
        int g = lane >> 2, tg = lane & 3;
        int n = n8 * 8 + g;
        int k0 = 32 * sp + 2 * tg;
        int k1 = k0 + 16;
        uint4 v;
        v.x = pack2(w1[(k0)      * 256 + n], w1[(k0 + 1)  * 256 + n]);
        v.y = pack2(w1[(k0 + 8)  * 256 + n], w1[(k0 + 9)  * 256 + n]);
        v.z = pack2(w1[(k1)      * 256 + n], w1[(k1 + 1)  * 256 + n]);
        v.w = pack2(w1[(k1 + 8)  * 256 + n], w1[(k1 + 9)  * 256 + n]);
        g_w1B[i] = v;
    }
    int j = i - 32 * SP1 * 32;
    if (j >= 0 && j < 32 * SP2 * 32) {
        int n8 = j / (SP2 * 32);
        int rem = j % (SP2 * 32);
        int sp = rem >> 5, lane = rem & 31;
        int g = lane >> 2, tg = lane & 3;
        int n = n8 * 8 + g;
        int k0 = 32 * sp + 2 * tg;
        int k1 = k0 + 16;
        uint4 v;
        v.x = pack2(w2[(k0)      * 256 + n], w2[(k0 + 1)  * 256 + n]);
        v.y = pack2(w2[(k0 + 8)  * 256 + n], w2[(k0 + 9)  * 256 + n]);
        v.z = pack2(w2[(k1)      * 256 + n], w2[(k1 + 1)  * 256 + n]);
        v.w = pack2(w2[(k1 + 8)  * 256 + n], w2[(k1 + 9)  * 256 + n]);
        g_w2B[j] = v;
    }
}

// ---------------------------------------------------------------- gemm core
template <int KS>
__device__ __forceinline__ void gemm_layer(const uint4* __restrict__ Wb,
                                           const uint4* __restrict__ smA4,
                                           int warp_n, int lane,
                                           float acc[4][4][4]) {
    constexpr int SP = KS / 2;
    const uint4* bptr[4];
#pragma unroll
    for (int nf = 0; nf < 4; nf++)
        bptr[nf] = Wb + (size_t)((warp_n * 4 + nf) * SP) * 32 + lane;

    uint4 bb[2][4];
#pragma unroll
    for (int nf = 0; nf < 4; nf++) bb[0][nf] = bptr[nf][0];

#pragma unroll
    for (int sp = 0; sp < SP; sp++) {
        const int cur = sp & 1;
        if (sp + 1 < SP) {
#pragma unroll
            for (int nf = 0; nf < 4; nf++)
                bb[cur ^ 1][nf] = bptr[nf][(sp + 1) * 32];
        }
#pragma unroll
        for (int h = 0; h < 2; h++) {
            const int s = 2 * sp + h;
            uint32_t a[4][4];
#pragma unroll
            for (int mf = 0; mf < 4; mf++) {
                uint4 av = smA4[(mf * KS + s) * 32 + lane];
                a[mf][0] = av.x; a[mf][1] = av.y; a[mf][2] = av.z; a[mf][3] = av.w;
            }
#pragma unroll
            for (int mf = 0; mf < 4; mf++)
#pragma unroll
                for (int nf = 0; nf < 4; nf++) {
                    uint32_t b0 = h ? bb[cur][nf].z : bb[cur][nf].x;
                    uint32_t b1 = h ? bb[cur][nf].w : bb[cur][nf].y;
                    mma16(acc[mf][nf], a[mf], b0, b1);
                }
        }
    }
}

// ---------------------------------------------------------------- main kernel
__global__ __launch_bounds__(256, 2)
void courier_main(const float* __restrict__ xy, const float* __restrict__ tin,
                  const float* __restrict__ w_sx, const float* __restrict__ b_sx,
                  const float* __restrict__ w_cx, const float* __restrict__ b_cx,
                  const float* __restrict__ w_sy, const float* __restrict__ b_sy,
                  const float* __restrict__ w_cy, const float* __restrict__ b_cy,
                  const float* __restrict__ w_t,  const float* __restrict__ b_t,
                  const float* __restrict__ b1,   const float* __restrict__ b2,
                  float* __restrict__ out) {
    extern __shared__ float sm[];
    uint4*  smA1 = (uint4*)(sm + SM_A1);
    uint4*  smA2 = (uint4*)(sm + SM_A2);
    float* sm_fr = sm + SM_FR;
    float* sm_wt = sm + SM_WT;
    float* sm_bt = sm + SM_BT;
    float* sm_b1 = sm + SM_B1;
    float* sm_b2 = sm + SM_B2;
    float* sm_x  = sm + SM_X;
    float* sm_y  = sm + SM_Y;
    float* sm_t  = sm + SM_T;

    const int tid    = threadIdx.x;
    const int lane   = tid & 31;
    const int warp_n = tid >> 5;          // 0..7

    // ---- stage small params + per-row inputs ----
    if (tid < 64) {
        int row = blockIdx.x * 64 + tid;
        float2 p = *(const float2*)(xy + 2 * row);
        sm_x[tid] = p.x;
        sm_y[tid] = p.y;
        sm_t[tid] = tin[row];
    }
    if (tid < 128) {
        sm_wt[tid] = w_t[tid];
        sm_bt[tid] = b_t[tid];
    }
    if (tid < 64) {
        sm_fr[tid]       = w_sx[tid];  sm_fr[64 + tid]  = b_sx[tid];
        sm_fr[128 + tid] = w_cx[tid];  sm_fr[192 + tid] = b_cx[tid];
        sm_fr[256 + tid] = w_sy[tid];  sm_fr[320 + tid] = b_sy[tid];
        sm_fr[384 + tid] = w_cy[tid];  sm_fr[448 + tid] = b_cy[tid];
    }
    sm_b1[tid] = b1[tid];
    sm_b2[tid] = b2[tid];
    __syncthreads();

    // ---- generate embedding A1 [64 x 384] FRAGMENT-NATIVE ----
    // warp w owns mt = w&3, k-steps s0..s0+11 (s0 = (w>>2)*12).
    // Each thread fills one uint4 fragment element per step:
    //   x = {emb(r0,k0),   emb(r0,k0+1)}   y = {emb(r1,k0),   emb(r1,k0+1)}
    //   z = {emb(r0,k0+8), emb(r0,k0+9)}   w = {emb(r1,k0+8), emb(r1,k0+9)}
    // with r0 = mt*16+g, r1 = r0+8, k0 = 16s+2tg. Store is thread-local,
    // warp-coalesced STS.128. A k16 fragment never crosses a 64-col region,
    // so the region branch is warp-uniform.
    {
        const int mt = warp_n & 3;
        const int s0 = (warp_n >> 2) * 12;
        const int g = lane >> 2, tg = lane & 3;
        const int r0 = mt * 16 + g, r1 = r0 + 8;
        const float xv0 = sm_x[r0], yv0 = sm_y[r0], tv0 = sm_t[r0];
        const float xv1 = sm_x[r1], yv1 = sm_y[r1], tv1 = sm_t[r1];

        auto embval = [&](int c, float xv, float yv, float tv) -> float {
            if (c < 64)  return __sinf(fmaf(xv, sm_fr[c], sm_fr[64 + c]));
            if (c < 128) { int i = c - 64;  return __cosf(fmaf(xv, sm_fr[128 + i], sm_fr[192 + i])); }
            if (c < 192) { int i = c - 128; return __sinf(fmaf(yv, sm_fr[256 + i], sm_fr[320 + i])); }
            if (c < 256) { int i = c - 192; return __cosf(fmaf(yv, sm_fr[384 + i], sm_fr[448 + i])); }
            int i = c - 256; return lrelu(fmaf(tv, sm_wt[i], sm_bt[i]));
        };

#pragma unroll
        for (int j = 0; j < 12; j++) {
            int s = s0 + j;
            int k0 = 16 * s + 2 * tg;
            uint4 st;
            st.x = pack2(embval(k0,     xv0, yv0, tv0), embval(k0 + 1, xv0, yv0, tv0));
            st.y = pack2(embval(k0,     xv1, yv1, tv1), embval(k0 + 1, xv1, yv1, tv1));
            st.z = pack2(embval(k0 + 8, xv0, yv0, tv0), embval(k0 + 9, xv0, yv0, tv0));
            st.w = pack2(embval(k0 + 8, xv1, yv1, tv1), embval(k0 + 9, xv1, yv1, tv1));
            smA1[(mt * KS1 + s) * 32 + lane] = st;
        }
    }
    __syncthreads();

    // ---- layer 1 ----
    float acc[4][4][4];
#pragma unroll
    for (int mf = 0; mf < 4; mf++)
#pragma unroll
        for (int nf = 0; nf < 4; nf++)
#pragma unroll
            for (int j = 0; j < 4; j++) acc[mf][nf][j] = 0.f;

    gemm_layer<KS1>(g_w1B, smA1, warp_n, lane, acc);

    // ---- epilogue 1: bias + lrelu + fp16 -> A2 (separate buffer, no WAR sync) ----
    {
        const int tg = lane & 3;
#pragma unroll
        for (int mf = 0; mf < 4; mf++) {
#pragma unroll
            for (int e = 0; e < 2; e++) {
                int col0 = warp_n * 32 + (2 * e) * 8 + 2 * tg;
                int col1 = col0 + 8;
                uint4 st;
                st.x = pack2(lrelu(acc[mf][2*e][0]   + sm_b1[col0]),
                             lrelu(acc[mf][2*e][1]   + sm_b1[col0 + 1]));
                st.y = pack2(lrelu(acc[mf][2*e][2]   + sm_b1[col0]),
                             lrelu(acc[mf][2*e][3]   + sm_b1[col0 + 1]));
                st.z = pack2(lrelu(acc[mf][2*e+1][0] + sm_b1[col1]),
                             lrelu(acc[mf][2*e+1][1] + sm_b1[col1 + 1]));
                st.w = pack2(lrelu(acc[mf][2*e+1][2] + sm_b1[col1]),
                             lrelu(acc[mf][2*e+1][3] + sm_b1[col1 + 1]));
                int s2 = warp_n * 2 + e;
                smA2[(mf * KS2 + s2) * 32 + lane] = st;
            }
        }
    }
    __syncthreads();

    // ---- layer 2 ----
#pragma unroll
    for (int mf = 0; mf < 4; mf++)
#pragma unroll
        for (int nf = 0; nf < 4; nf++)
#pragma unroll
            for (int j = 0; j < 4; j++) acc[mf][nf][j] = 0.f;

    gemm_layer<KS2>(g_w2B, smA2, warp_n, lane, acc);

    // ---- final epilogue: bias + lrelu, float2 stores to gmem ----
    {
        const int g  = lane >> 2;
        const int tg = lane & 3;
        float* obase = out + (size_t)blockIdx.x * 64 * 256;
#pragma unroll
        for (int mf = 0; mf < 4; mf++) {
#pragma unroll
            for (int nf = 0; nf < 4; nf++) {
                int row = mf * 16 + g;
                int col = warp_n * 32 + nf * 8 + 2 * tg;
                float2 v0, v1;
                v0.x = lrelu(acc[mf][nf][0] + sm_b2[col]);
                v0.y = lrelu(acc[mf][nf][1] + sm_b2[col + 1]);
                v1.x = lrelu(acc[mf][nf][2] + sm_b2[col]);
                v1.y = lrelu(acc[mf][nf][3] + sm_b2[col + 1]);
                *(float2*)(obase + row * 256 + col)       = v0;
                *(float2*)(obase + (row + 8) * 256 + col) = v1;
            }
        }
    }
}

// ---------------------------------------------------------------- launcher
extern "C" void kernel_launch(void* const* d_in, const int* in_sizes, int n_in,
                              void* d_out, int out_size) {
    const float* xy   = (const float*)d_in[0];
    const float* t    = (const float*)d_in[1];
    const float* w_sx = (const float*)d_in[2];
    const float* b_sx = (const float*)d_in[3];
    const float* w_cx = (const float*)d_in[4];
    const float* b_cx = (const float*)d_in[5];
    const float* w_sy = (const float*)d_in[6];
    const float* b_sy = (const float*)d_in[7];
    const float* w_cy = (const float*)d_in[8];
    const float* b_cy = (const float*)d_in[9];
    const float* w_t  = (const float*)d_in[10];
    const float* b_t  = (const float*)d_in[11];
    const float* w1   = (const float*)d_in[12];
    const float* b1   = (const float*)d_in[13];
    const float* w2   = (const float*)d_in[14];
    const float* b2   = (const float*)d_in[15];
    float* out = (float*)d_out;

    courier_prep<<<80, 256>>>(w1, w2);

    static bool attr_set = false;
    if (!attr_set) {
        cudaFuncSetAttribute(courier_main, cudaFuncAttributeMaxDynamicSharedMemorySize,
                             SMEM_BYTES);
        attr_set = true;
    }

    courier_main<<<4096, 256, SMEM_BYTES>>>(xy, t, w_sx, b_sx, w_cx, b_cx,
                                            w_sy, b_sy, w_cy, b_cy,
                                            w_t, b_t, b1, b2, out);
}